// round 13
// baseline (speedup 1.0000x reference)
#include <cuda_runtime.h>
#include <cuda_bf16.h>

#define TS 64                    // tile side (pixels)
#define MAX_TILES 4096           // (4096/64)^2
#define CAP 512                  // slots per tile (mean ~52 for 200k uniform boxes)
#define NSLICE 4

// Scratch (static zero-init). paint_kernel resets each tile's cursor to 0
// after reading it, so the cursor array is all-zero at the start of every
// call / graph replay — deterministic, no separate zeroing pass needed.
__device__ int  g_cursor[MAX_TILES];
__device__ int2 g_bins[MAX_TILES * CAP];   // {.x = (cy<<16)|cx, .y = boxIdx}

// ---------------- pass 1: bin box payloads into per-tile lists (one ty-band) ----------------
__global__ void __launch_bounds__(256)
scatter_kernel(const float4* __restrict__ boxes,
               const int* __restrict__ wp, const int* __restrict__ hp,
               int n_boxes, int slice) {
    int i = blockIdx.x * blockDim.x + threadIdx.x;
    if (i >= n_boxes) return;
    const int w = *wp, h = *hp;
    const int tw = (w + TS - 1) / TS;
    const int th = (h + TS - 1) / TS;
    const int ty_lo = (slice * th) / NSLICE;
    const int ty_hi = ((slice + 1) * th) / NSLICE;

    float4 b = __ldg(&boxes[i]);
    int cx = (int)(b.x * (float)w);
    int cy = (int)(b.y * (float)h);
    if (cx < 0 || cx >= w || cy < 0 || cy >= h) return;

    int2 e = make_int2((cy << 16) | cx, i);

    bool valid = (cx >= 1) & (cx <= w - 2) & (cy >= 1) & (cy <= h - 2);
    if (!valid) {
        int ty = cy / TS;
        if (ty >= ty_lo && ty < ty_hi) {
            int t = ty * tw + (cx / TS);
            int slot = atomicAdd(&g_cursor[t], 1);
            if (slot < CAP) g_bins[t * CAP + slot] = e;
        }
    } else {
        int tx0 = (cx - 1) / TS, tx1 = (cx + 1) / TS;
        int ty0 = (cy - 1) / TS, ty1 = (cy + 1) / TS;
        for (int ty = ty0; ty <= ty1; ty++) {
            if (ty < ty_lo || ty >= ty_hi) continue;
            for (int tx = tx0; tx <= tx1; tx++) {
                int t = ty * tw + tx;
                int slot = atomicAdd(&g_cursor[t], 1);
                if (slot < CAP) g_bins[t * CAP + slot] = e;
            }
        }
    }
}

// ---------------- pass 2: per-tile SMEM composite + streamed output (one ty-band) ----------------
__global__ void __launch_bounds__(256)
paint_kernel(const float4* __restrict__ boxes,
             const float* __restrict__ mount,
             const int* __restrict__ wp, const int* __restrict__ hp,
             float* __restrict__ out, int slice) {
    __shared__ int s_heat[TS * TS];   // float bits; atomicMax(int) == float max (vals >= 0)
    __shared__ int s_win[TS * TS];    // winner = boxIdx+1 (0 = empty)

    const int w = *wp, h = *hp;
    const int tw = (w + TS - 1) / TS, th = (h + TS - 1) / TS;
    const int hw = w * h;
    const int ty_lo = (slice * th) / NSLICE;
    const int ty_hi = ((slice + 1) * th) / NSLICE;
    const int t_begin = ty_lo * tw, t_end = ty_hi * tw;

    float m[9];
#pragma unroll
    for (int j = 0; j < 9; j++) m[j] = __ldg(&mount[j]);

    for (int t = t_begin + blockIdx.x; t < t_end; t += gridDim.x) {
        // ---- prefetch bin entries BEFORE zeroing smem (latency hides under STS) ----
        int c = g_cursor[t];
        const int cnt = (c < CAP) ? c : CAP;
        const int off = t * CAP;
        int2 e0 = make_int2(0, -1), e1 = make_int2(0, -1);
        if ((int)threadIdx.x < cnt)        e0 = g_bins[off + threadIdx.x];
        if ((int)threadIdx.x + 256 < cnt)  e1 = g_bins[off + threadIdx.x + 256];

        // vectorized smem zero (int4)
        const int4 z4 = make_int4(0, 0, 0, 0);
        for (int k = threadIdx.x; k < TS * TS / 4; k += 256) {
            ((int4*)s_heat)[k] = z4;
            ((int4*)s_win)[k]  = z4;
        }
        if (threadIdx.x == 0) g_cursor[t] = 0;   // self-reset scratch for next call
        __syncthreads();

        const int ty = t / tw, tx = t % tw;
        const int x0 = tx * TS, y0 = ty * TS;

#pragma unroll
        for (int p = 0; p < 2; p++) {
            int2 e = (p == 0) ? e0 : e1;
            if (e.y < 0) continue;
            int cx = e.x & 0xFFFF;
            int cy = e.x >> 16;

            // sizemap winner election (center cell in this tile only)
            if (cx / TS == tx && cy / TS == ty)
                atomicMax(&s_win[(cy - y0) * TS + (cx - x0)], e.y + 1);

            // 3x3 gaussian stamp (only when full window fits in the image)
            if (cx >= 1 && cx <= w - 2 && cy >= 1 && cy <= h - 2) {
#pragma unroll
                for (int dy = -1; dy <= 1; dy++) {
                    int gy = cy + dy - y0;
                    if (gy < 0 || gy >= TS) continue;
#pragma unroll
                    for (int dx = -1; dx <= 1; dx++) {
                        int gx = cx + dx - x0;
                        if (gx < 0 || gx >= TS) continue;
                        atomicMax(&s_heat[gy * TS + gx],
                                  __float_as_int(m[(dy + 1) * 3 + (dx + 1)]));
                    }
                }
            }
        }
        __syncthreads();

        // stream the tile: heat + size0 + size1, float4 coalesced
        for (int idx = threadIdx.x; idx < TS * TS / 4; idx += 256) {
            int row = idx / (TS / 4);
            int c4  = idx % (TS / 4);
            int gy  = y0 + row;
            int gxb = x0 + c4 * 4;

            float4 hv = ((float4*)s_heat)[idx];
            int4  wv4 = ((int4*)s_win)[idx];
            float4 s0 = make_float4(0.f, 0.f, 0.f, 0.f);
            float4 s1 = make_float4(0.f, 0.f, 0.f, 0.f);
#pragma unroll
            for (int q = 0; q < 4; q++) {
                int wv = ((int*)&wv4)[q];
                if (wv > 0) {
                    float4 bb = __ldg(&boxes[wv - 1]);   // rare: winner cells only
                    ((float*)&s0)[q] = bb.z;
                    ((float*)&s1)[q] = bb.w;
                }
            }
            if (gy < h && gxb + 3 < w) {
                int g = gy * w + gxb;
                *(float4*)(out + g)          = hv;
                *(float4*)(out + hw + g)     = s0;
                *(float4*)(out + 2 * hw + g) = s1;
            } else {
#pragma unroll
                for (int q = 0; q < 4; q++) {
                    int gx = gxb + q;
                    if (gy < h && gx < w) {
                        int g = gy * w + gx;
                        out[g]          = ((float*)&hv)[q];
                        out[hw + g]     = ((float*)&s0)[q];
                        out[2 * hw + g] = ((float*)&s1)[q];
                    }
                }
            }
        }
        __syncthreads();   // protect smem re-zero of next tile iteration
    }
}

extern "C" void kernel_launch(void* const* d_in, const int* in_sizes, int n_in,
                              void* d_out, int out_size) {
    const float4* boxes = (const float4*)d_in[0];  // [N,4] cx,cy,w,h
    const float*  mount = (const float*)d_in[1];   // [3,3]
    const int*    wp    = (const int*)d_in[2];     // scalar w
    const int*    hp    = (const int*)d_in[3];     // scalar h
    float* out = (float*)d_out;                    // [hw heat | hw size0 | hw size1]

    int n_boxes = in_sizes[0] / 4;

    // One-time handles (no device memory allocated here).
    static cudaStream_t sB = []() {
        cudaStream_t s; cudaStreamCreateWithFlags(&s, cudaStreamNonBlocking); return s;
    }();
    static cudaEvent_t eRoot = []() {
        cudaEvent_t e; cudaEventCreateWithFlags(&e, cudaEventDisableTiming); return e;
    }();
    static cudaEvent_t eS[NSLICE] = {};
    if (!eS[0])
        for (int s = 0; s < NSLICE; s++)
            cudaEventCreateWithFlags(&eS[s], cudaEventDisableTiming);

    const int threads = 256;
    int bblocks = (n_boxes + threads - 1) / threads;

    // fork: sB binned slices run ahead of the paint stream
    cudaEventRecord(eRoot, 0);
    cudaStreamWaitEvent(sB, eRoot, 0);

    for (int s = 0; s < NSLICE; s++) {
        scatter_kernel<<<bblocks, threads, 0, sB>>>(boxes, wp, hp, n_boxes, s);
        cudaEventRecord(eS[s], sB);
    }
    for (int s = 0; s < NSLICE; s++) {
        cudaStreamWaitEvent(0, eS[s], 0);   // paint slice s needs only scatter slice s
        paint_kernel<<<MAX_TILES / NSLICE, threads>>>(boxes, mount, wp, hp, out, s);
    }
}